// round 11
// baseline (speedup 1.0000x reference)
#include <cuda_runtime.h>
#include <cuda_fp16.h>
#include <cstdint>
#include <math.h>

#define B_  1024
#define V_  50257
#define E_  128
#define NT_ 393          // ceil(V_/128)
#define VP_ (NT_ * 128)  // 50304 padded rows
#define GX_ 38           // n-split: 38 x 4 = 152 CTAs = 1 per SM

// ---- scratch (no allocations allowed) ----
__device__ int     g_idx[B_];
__device__ __half  g_yh[B_ * E_];
__device__ __half  g_negh[(size_t)VP_ * E_];      // padded half copy of NEGEMBEDM
__device__ float2  g_part2[(size_t)B_ * NT_ * 4]; // per-(row, tile, warp_n) partials
__device__ float   g_lse[B_];

__device__ __forceinline__ uint32_t smem_u32(const void* p) {
    uint32_t a;
    asm("{ .reg .u64 t; cvta.to.shared.u64 t, %1; cvt.u32.u64 %0, t; }"
        : "=r"(a) : "l"(p));
    return a;
}

// ---------------- K1: fused conv(NEG->half, padded) + one-hot index scan ----
__global__ void prep_kernel(const float4* __restrict__ neg4,
                            const float4* __restrict__ xs4) {
    if (blockIdx.x < 1024) {
        const long n8 = (long)VP_ * E_ / 8;
        for (long i = blockIdx.x * (long)blockDim.x + threadIdx.x; i < n8;
             i += 1024L * blockDim.x) {
            long row = (i * 8) / E_;
            if (row < V_) {
                float4 v0 = neg4[i * 2];
                float4 v1 = neg4[i * 2 + 1];
                __half2 h0 = __float22half2_rn(make_float2(v0.x, v0.y));
                __half2 h1 = __float22half2_rn(make_float2(v0.z, v0.w));
                __half2 h2 = __float22half2_rn(make_float2(v1.x, v1.y));
                __half2 h3 = __float22half2_rn(make_float2(v1.z, v1.w));
                uint4 o = make_uint4(*reinterpret_cast<uint32_t*>(&h0),
                                     *reinterpret_cast<uint32_t*>(&h1),
                                     *reinterpret_cast<uint32_t*>(&h2),
                                     *reinterpret_cast<uint32_t*>(&h3));
                *reinterpret_cast<uint4*>(g_negh + i * 8) = o;
            } else {
                *reinterpret_cast<uint4*>(g_negh + i * 8) = make_uint4(0, 0, 0, 0);
            }
        }
    } else {
        const long n4 = (long)B_ * V_ / 4;
        for (long i = (blockIdx.x - 1024) * (long)blockDim.x + threadIdx.x; i < n4;
             i += 2048L * blockDim.x) {
            float4 v = xs4[i];
            if (v.x != 0.f || v.y != 0.f || v.z != 0.f || v.w != 0.f) {
                float vals[4] = {v.x, v.y, v.z, v.w};
                long base = i * 4;
#pragma unroll
                for (int j = 0; j < 4; j++) {
                    if (vals[j] != 0.f) {
                        long p = base + j;
                        int  b = (int)(p / V_);
                        g_idx[b] = (int)(p - (long)b * V_);
                    }
                }
            }
        }
    }
}

// ---------------- K2: y[b] = EMBEDM[idx[b]] @ metric -> half ----------------
__global__ void embed_metric_kernel(const float* __restrict__ EMB,
                                    const float* __restrict__ metric) {
    __shared__ float xe[E_];
    const int b = blockIdx.x, t = threadIdx.x;   // 128 threads
    const int idx = g_idx[b];
    xe[t] = EMB[(size_t)idx * E_ + t];
    __syncthreads();
    float acc = 0.f;
#pragma unroll 8
    for (int k = 0; k < E_; k++) acc += xe[k] * metric[k * E_ + t];
    g_yh[b * E_ + t] = __float2half_rn(acc);
}

// ---------------- K3: persistent fp16 GEMM, two passes, 256-row super-block -
// Each CTA owns TWO A tiles (256 rows) and runs the mainloop twice per B tile
// -> B L2 traffic halves.  256 threads, 8 warps 2(m) x 4(n), warp tile 64x32.
// smem: A0 @0 | A1 @32768 | B0/B1/B2 @65536 | C float[128][132] @163840
#define SM_A   0
#define SM_B0  65536
#define SM_C   163840
#define CPAD   132
#define SMEM_BYTES (163840 + 128 * CPAD * 4)   // 231424

__device__ __forceinline__ uint32_t swz(int row, int c8) {
    return (uint32_t)(row * 256 + ((c8 ^ (row & 7)) << 4));
}

__device__ __forceinline__ void mainloop(uint32_t aB, uint32_t bB,
                                         float c[4][4][4],
                                         int lane, int warp_m, int warp_n) {
#pragma unroll
    for (int mi = 0; mi < 4; mi++)
#pragma unroll
        for (int ni = 0; ni < 4; ni++)
#pragma unroll
            for (int j = 0; j < 4; j++) c[mi][ni][j] = 0.f;

#pragma unroll
    for (int ks = 0; ks < 8; ks++) {
        const int c8a = ks * 2 + (lane >> 4);
        uint32_t a[4][4], b[4][2];
#pragma unroll
        for (int mi = 0; mi < 4; mi++) {
            int row = warp_m * 64 + mi * 16 + (lane & 15);
            uint32_t addr = aB + swz(row, c8a);
            asm volatile("ldmatrix.sync.aligned.m8n8.x4.shared.b16 "
                         "{%0,%1,%2,%3}, [%4];"
                         : "=r"(a[mi][0]), "=r"(a[mi][1]),
                           "=r"(a[mi][2]), "=r"(a[mi][3]) : "r"(addr));
        }
#pragma unroll
        for (int j = 0; j < 2; j++) {
            const int g = lane >> 3;
            int ni_x = 2 * j + (g >> 1);
            int half = g & 1;
            int nrow = warp_n * 32 + ni_x * 8 + (lane & 7);
            uint32_t addr = bB + swz(nrow, ks * 2 + half);
            asm volatile("ldmatrix.sync.aligned.m8n8.x4.shared.b16 "
                         "{%0,%1,%2,%3}, [%4];"
                         : "=r"(b[2 * j][0]), "=r"(b[2 * j][1]),
                           "=r"(b[2 * j + 1][0]), "=r"(b[2 * j + 1][1])
                         : "r"(addr));
        }
#pragma unroll
        for (int mi = 0; mi < 4; mi++)
#pragma unroll
            for (int ni = 0; ni < 4; ni++)
                asm volatile(
                    "mma.sync.aligned.m16n8k16.row.col.f32.f16.f16.f32 "
                    "{%0,%1,%2,%3},{%4,%5,%6,%7},{%8,%9},{%0,%1,%2,%3};"
                    : "+f"(c[mi][ni][0]), "+f"(c[mi][ni][1]),
                      "+f"(c[mi][ni][2]), "+f"(c[mi][ni][3])
                    : "r"(a[mi][0]), "r"(a[mi][1]), "r"(a[mi][2]), "r"(a[mi][3]),
                      "r"(b[ni][0]), "r"(b[ni][1]));
    }
}

template<bool FULL>
__device__ __forceinline__ void partials(const float c[4][4][4], int nvalid,
                                         int m0, int n0, int warp_m, int warp_n,
                                         int qid, int tig, int nt) {
#pragma unroll
    for (int mi = 0; mi < 4; mi++) {
        const int r0 = m0 + warp_m * 64 + mi * 16 + qid;
        float mxa = -INFINITY, mxb = -INFINITY;
        float sa = 0.f, sb = 0.f;
#pragma unroll
        for (int ni = 0; ni < 4; ni++) {
            const int cc = warp_n * 32 + ni * 8 + tig * 2;
            if (FULL || cc < nvalid) {
                mxa = fmaxf(mxa, c[mi][ni][0]);
                mxb = fmaxf(mxb, c[mi][ni][2]);
            }
            if (FULL || cc + 1 < nvalid) {
                mxa = fmaxf(mxa, c[mi][ni][1]);
                mxb = fmaxf(mxb, c[mi][ni][3]);
            }
        }
        mxa = fmaxf(mxa, __shfl_xor_sync(0xffffffffu, mxa, 1));
        mxa = fmaxf(mxa, __shfl_xor_sync(0xffffffffu, mxa, 2));
        mxb = fmaxf(mxb, __shfl_xor_sync(0xffffffffu, mxb, 1));
        mxb = fmaxf(mxb, __shfl_xor_sync(0xffffffffu, mxb, 2));
#pragma unroll
        for (int ni = 0; ni < 4; ni++) {
            const int cc = warp_n * 32 + ni * 8 + tig * 2;
            if (FULL || cc < nvalid)     { sa += __expf(c[mi][ni][0] - mxa);
                                           sb += __expf(c[mi][ni][2] - mxb); }
            if (FULL || cc + 1 < nvalid) { sa += __expf(c[mi][ni][1] - mxa);
                                           sb += __expf(c[mi][ni][3] - mxb); }
        }
        sa += __shfl_xor_sync(0xffffffffu, sa, 1);
        sa += __shfl_xor_sync(0xffffffffu, sa, 2);
        sb += __shfl_xor_sync(0xffffffffu, sb, 1);
        sb += __shfl_xor_sync(0xffffffffu, sb, 2);
        if (tig == 0) {
            g_part2[((size_t)r0 * NT_ + nt) * 4 + warp_n]       = make_float2(mxa, sa);
            g_part2[((size_t)(r0 + 8) * NT_ + nt) * 4 + warp_n] = make_float2(mxb, sb);
        }
    }
}

// stage register C -> smem (float2, <=2-way conflicts)
__device__ __forceinline__ void stageC(const float c[4][4][4], float* Cs,
                                       int warp_m, int warp_n, int qid, int tig) {
#pragma unroll
    for (int mi = 0; mi < 4; mi++) {
        const int r0 = warp_m * 64 + mi * 16 + qid;
        float* c0p = Cs + r0 * CPAD + warp_n * 32 + tig * 2;
#pragma unroll
        for (int ni = 0; ni < 4; ni++) {
            *reinterpret_cast<float2*>(c0p + ni * 8) =
                make_float2(c[mi][ni][0], c[mi][ni][1]);
            *reinterpret_cast<float2*>(c0p + ni * 8 + 8 * CPAD) =
                make_float2(c[mi][ni][2], c[mi][ni][3]);
        }
    }
}

// coalesced copy smem C -> out with lse subtraction
__device__ __forceinline__ void copyC(const float* Cs, float* __restrict__ out,
                                      int m0, int n0, int nvalid,
                                      int wid, int lane) {
    if (nvalid == 128) {
#pragma unroll
        for (int j = 0; j < 16; j++) {
            const int row = (wid << 4) + j;          // row%4 == j%4
            const float ls = g_lse[m0 + row];
            const float* cs = Cs + row * CPAD;
            float* ob = out + (size_t)(m0 + row) * V_ + n0;
            if ((j & 3) == 0) {                      // 16B-aligned: float4
                int col = lane << 2;
                *reinterpret_cast<float4*>(ob + col) =
                    make_float4(cs[col] - ls, cs[col + 1] - ls,
                                cs[col + 2] - ls, cs[col + 3] - ls);
            } else if (!(j & 1)) {                   // 8B-aligned: float2
#pragma unroll
                for (int k = 0; k < 2; k++) {
                    int col = ((k << 5) + lane) << 1;
                    *reinterpret_cast<float2*>(ob + col) =
                        make_float2(cs[col] - ls, cs[col + 1] - ls);
                }
            } else {                                 // odd: head/tail + body
                if (lane == 0)  ob[0]   = cs[0]   - ls;
                if (lane == 31) ob[127] = cs[127] - ls;
#pragma unroll
                for (int k = 0; k < 2; k++) {
                    int i2 = (k << 5) + lane;
                    if (i2 < 63) {
                        int col = 1 + (i2 << 1);
                        *reinterpret_cast<float2*>(ob + col) =
                            make_float2(cs[col] - ls, cs[col + 1] - ls);
                    }
                }
            }
        }
    } else {
        for (int j = 0; j < 16; j++) {
            const int row = (wid << 4) + j;
            const float ls = g_lse[m0 + row];
            const float* cs = Cs + row * CPAD;
            float* ob = out + (size_t)(m0 + row) * V_ + n0;
            for (int col = lane; col < nvalid; col += 32)
                ob[col] = cs[col] - ls;
        }
    }
}

template<bool WRITE>
__global__ void __launch_bounds__(256, 1)
gemm_pass(float* __restrict__ out) {
    extern __shared__ char smc[];
    const uint32_t sbase = smem_u32(smc);
    float* Cs = reinterpret_cast<float*>(smc + SM_C);

    const int tid = threadIdx.x;
    const int wid = tid >> 5, lane = tid & 31;
    const int warp_m = wid & 1, warp_n = wid >> 1;   // 2(m) x 4(n)
    const int qid = lane >> 2, tig = lane & 3;
    const int m0a = blockIdx.y * 256;                // 256-row super-block

    auto issueB = [&](int nt, int buf) {
        if (nt < NT_) {
            const int n0 = nt * 128;
            const uint32_t d0 = sbase + SM_B0 + (buf << 15);
#pragma unroll
            for (int f = tid; f < 2048; f += 256) {
                int row = f >> 4, c8 = f & 15;
                uint32_t dst = d0 + swz(row, c8);
                const char* src = reinterpret_cast<const char*>(g_negh)
                                + (size_t)(n0 + row) * 256 + c8 * 16;
                asm volatile("cp.async.cg.shared.global [%0], [%1], 16;"
                             :: "r"(dst), "l"(src) : "memory");
            }
        }
        asm volatile("cp.async.commit_group;" ::: "memory");
    };

    issueB(blockIdx.x, 0);
    issueB(blockIdx.x + GX_, 1);

    // ---- stage BOTH A tiles (rows m0a .. m0a+255) into swizzled smem ----
#pragma unroll
    for (int f = tid; f < 4096; f += 256) {
        int mb = f >> 11, r = (f & 2047) >> 4, c8 = f & 15;
        uint4 v = *reinterpret_cast<const uint4*>(
            g_yh + (m0a + mb * 128 + r) * E_ + c8 * 8);
        *reinterpret_cast<uint4*>(smc + SM_A + (mb << 15) + swz(r, c8)) = v;
    }

    int idx = 0;
    for (int nt = blockIdx.x; nt < NT_; nt += GX_, idx++) {
        asm volatile("cp.async.wait_group 1;" ::: "memory");
        __syncthreads();   // B buffer visible; also protects Cs from last copy

        const int bsel = idx - (idx / 3) * 3;
        const uint32_t bB = sbase + SM_B0 + (bsel << 15);
        const int n0 = nt * 128;
        const int nvalid = min(128, V_ - n0);
        const int nbuf = (bsel + 2 >= 3) ? bsel - 1 : bsel + 2;

        float c[4][4][4];

        // ---- m-block 0 ----
        mainloop(sbase + SM_A, bB, c, lane, warp_m, warp_n);
        if (!WRITE) {
            if (nvalid == 128) partials<true >(c, nvalid, m0a, n0, warp_m, warp_n, qid, tig, nt);
            else               partials<false>(c, nvalid, m0a, n0, warp_m, warp_n, qid, tig, nt);
        } else {
            stageC(c, Cs, warp_m, warp_n, qid, tig);
            __syncthreads();
            copyC(Cs, out, m0a, n0, nvalid, wid, lane);
        }

        // ---- m-block 1 (same B tile) ----
        mainloop(sbase + SM_A + 32768, bB, c, lane, warp_m, warp_n);
        issueB(nt + 2 * GX_, nbuf);          // B tile fully consumed
        if (!WRITE) {
            if (nvalid == 128) partials<true >(c, nvalid, m0a + 128, n0, warp_m, warp_n, qid, tig, nt);
            else               partials<false>(c, nvalid, m0a + 128, n0, warp_m, warp_n, qid, tig, nt);
        } else {
            __syncthreads();                 // copy of m-block 0 done
            stageC(c, Cs, warp_m, warp_n, qid, tig);
            __syncthreads();
            copyC(Cs, out, m0a + 128, n0, nvalid, wid, lane);
        }
    }
}

// ---------------- K4: combine partials -> lse[b] ----------------------------
__global__ void lse_kernel() {
    const int b = blockIdx.x, t = threadIdx.x;   // 256 threads
    __shared__ float sm_[256], sl[256];
    const int NQ = NT_ * 2;                      // float4 count (= NT_*4/2)
    const float4* p4 = reinterpret_cast<const float4*>(
        g_part2 + (size_t)b * NT_ * 4);
    float m = -INFINITY, l = 0.f;
    for (int i = t; i < NQ; i += 256) {
        float4 v = p4[i];
        float nm = fmaxf(m, v.x);
        l = l * __expf(m - nm) + v.y * __expf(v.x - nm);
        m = nm;
        nm = fmaxf(m, v.z);
        l = l * __expf(m - nm) + v.w * __expf(v.z - nm);
        m = nm;
    }
    sm_[t] = m; sl[t] = l;
    __syncthreads();
    for (int s = 128; s > 0; s >>= 1) {
        if (t < s) {
            float m2 = sm_[t + s], l2 = sl[t + s];
            float nm = fmaxf(sm_[t], m2);
            sl[t] = sl[t] * __expf(sm_[t] - nm) + l2 * __expf(m2 - nm);
            sm_[t] = nm;
        }
        __syncthreads();
    }
    if (t == 0) g_lse[b] = sm_[0] + logf(sl[0]);
}

extern "C" void kernel_launch(void* const* d_in, const int* in_sizes, int n_in,
                              void* d_out, int out_size) {
    const float* xs     = (const float*)d_in[0];
    const float* metric = (const float*)d_in[1];
    const float* EMB    = (const float*)d_in[2];
    const float* NEG    = (const float*)d_in[3];
    float* out = (float*)d_out;

    prep_kernel<<<3072, 256>>>((const float4*)NEG, (const float4*)xs);
    embed_metric_kernel<<<B_, 128>>>(EMB, metric);

    cudaFuncSetAttribute(gemm_pass<false>,
                         cudaFuncAttributeMaxDynamicSharedMemorySize, SMEM_BYTES);
    cudaFuncSetAttribute(gemm_pass<true>,
                         cudaFuncAttributeMaxDynamicSharedMemorySize, SMEM_BYTES);

    gemm_pass<false><<<dim3(GX_, 4), 256, SMEM_BYTES>>>(out);
    lse_kernel<<<B_, 256>>>();
    gemm_pass<true ><<<dim3(GX_, 4), 256, SMEM_BYTES>>>(out);
}

// round 12
// speedup vs baseline: 1.0609x; 1.0609x over previous
#include <cuda_runtime.h>
#include <cuda_fp16.h>
#include <cstdint>
#include <math.h>

#define B_  1024
#define V_  50257
#define E_  128
#define NT_ 393          // ceil(V_/128)
#define VP_ (NT_ * 128)  // 50304 padded rows
#define GX_ 19           // n-split: 19 x 8 = 152 CTAs = 1 per SM

// ---- scratch (no allocations allowed) ----
__device__ int     g_idx[B_];
__device__ __half  g_yh[B_ * E_];
__device__ __half  g_negh[(size_t)VP_ * E_];      // padded half copy of NEGEMBEDM
__device__ float2  g_part2[(size_t)B_ * NT_ * 4]; // per-(row, tile, warp_n) partials
__device__ float   g_lse[B_];

__device__ __forceinline__ uint32_t smem_u32(const void* p) {
    uint32_t a;
    asm("{ .reg .u64 t; cvta.to.shared.u64 t, %1; cvt.u32.u64 %0, t; }"
        : "=r"(a) : "l"(p));
    return a;
}

// ---------------- K1: fused conv(NEG->half, padded) + one-hot index scan ----
__global__ void prep_kernel(const float4* __restrict__ neg4,
                            const float4* __restrict__ xs4) {
    if (blockIdx.x < 1024) {
        const long n8 = (long)VP_ * E_ / 8;
        for (long i = blockIdx.x * (long)blockDim.x + threadIdx.x; i < n8;
             i += 1024L * blockDim.x) {
            long row = (i * 8) / E_;
            if (row < V_) {
                float4 v0 = neg4[i * 2];
                float4 v1 = neg4[i * 2 + 1];
                __half2 h0 = __float22half2_rn(make_float2(v0.x, v0.y));
                __half2 h1 = __float22half2_rn(make_float2(v0.z, v0.w));
                __half2 h2 = __float22half2_rn(make_float2(v1.x, v1.y));
                __half2 h3 = __float22half2_rn(make_float2(v1.z, v1.w));
                uint4 o = make_uint4(*reinterpret_cast<uint32_t*>(&h0),
                                     *reinterpret_cast<uint32_t*>(&h1),
                                     *reinterpret_cast<uint32_t*>(&h2),
                                     *reinterpret_cast<uint32_t*>(&h3));
                *reinterpret_cast<uint4*>(g_negh + i * 8) = o;
            } else {
                *reinterpret_cast<uint4*>(g_negh + i * 8) = make_uint4(0, 0, 0, 0);
            }
        }
    } else {
        const long n4 = (long)B_ * V_ / 4;
        for (long i = (blockIdx.x - 1024) * (long)blockDim.x + threadIdx.x; i < n4;
             i += 2048L * blockDim.x) {
            float4 v = xs4[i];
            if (v.x != 0.f || v.y != 0.f || v.z != 0.f || v.w != 0.f) {
                float vals[4] = {v.x, v.y, v.z, v.w};
                long base = i * 4;
#pragma unroll
                for (int j = 0; j < 4; j++) {
                    if (vals[j] != 0.f) {
                        long p = base + j;
                        int  b = (int)(p / V_);
                        g_idx[b] = (int)(p - (long)b * V_);
                    }
                }
            }
        }
    }
}

// ---------------- K2: y[b] = EMBEDM[idx[b]] @ metric -> half ----------------
__global__ void embed_metric_kernel(const float* __restrict__ EMB,
                                    const float* __restrict__ metric) {
    __shared__ float xe[E_];
    const int b = blockIdx.x, t = threadIdx.x;   // 128 threads
    const int idx = g_idx[b];
    xe[t] = EMB[(size_t)idx * E_ + t];
    __syncthreads();
    float acc = 0.f;
#pragma unroll 8
    for (int k = 0; k < E_; k++) acc += xe[k] * metric[k * E_ + t];
    g_yh[b * E_ + t] = __float2half_rn(acc);
}

// ---------------- K3: persistent fp16 GEMM, two passes ----------------------
// Pass 1 (WRITE=false): mainloop + per-warp softmax partials, no stores.
// Pass 2 (WRITE=true):  mainloop + (score - lse) staged coalesced store.
// 256 threads, 8 warps in 2(m) x 4(n); warp tile 64x32.
// smem: A @0 (32KB) | B0/B1/B2 @32768+ (96KB) | C float[128][132] @131072
#define SM_A   0
#define SM_B0  32768
#define SM_C   131072
#define CPAD   132
#define SMEM_BYTES (131072 + 128 * CPAD * 4)   // 198656

__device__ __forceinline__ uint32_t swz(int row, int c8) {
    return (uint32_t)(row * 256 + ((c8 ^ (row & 7)) << 4));
}

__device__ __forceinline__ void mainloop(uint32_t aB, uint32_t bB,
                                         float c[4][4][4],
                                         int lane, int warp_m, int warp_n) {
#pragma unroll
    for (int mi = 0; mi < 4; mi++)
#pragma unroll
        for (int ni = 0; ni < 4; ni++)
#pragma unroll
            for (int j = 0; j < 4; j++) c[mi][ni][j] = 0.f;

#pragma unroll
    for (int ks = 0; ks < 8; ks++) {
        const int c8a = ks * 2 + (lane >> 4);
        uint32_t a[4][4], b[4][2];
#pragma unroll
        for (int mi = 0; mi < 4; mi++) {
            int row = warp_m * 64 + mi * 16 + (lane & 15);
            uint32_t addr = aB + swz(row, c8a);
            asm volatile("ldmatrix.sync.aligned.m8n8.x4.shared.b16 "
                         "{%0,%1,%2,%3}, [%4];"
                         : "=r"(a[mi][0]), "=r"(a[mi][1]),
                           "=r"(a[mi][2]), "=r"(a[mi][3]) : "r"(addr));
        }
#pragma unroll
        for (int j = 0; j < 2; j++) {
            const int g = lane >> 3;
            int ni_x = 2 * j + (g >> 1);
            int half = g & 1;
            int nrow = warp_n * 32 + ni_x * 8 + (lane & 7);
            uint32_t addr = bB + swz(nrow, ks * 2 + half);
            asm volatile("ldmatrix.sync.aligned.m8n8.x4.shared.b16 "
                         "{%0,%1,%2,%3}, [%4];"
                         : "=r"(b[2 * j][0]), "=r"(b[2 * j][1]),
                           "=r"(b[2 * j + 1][0]), "=r"(b[2 * j + 1][1])
                         : "r"(addr));
        }
#pragma unroll
        for (int mi = 0; mi < 4; mi++)
#pragma unroll
            for (int ni = 0; ni < 4; ni++)
                asm volatile(
                    "mma.sync.aligned.m16n8k16.row.col.f32.f16.f16.f32 "
                    "{%0,%1,%2,%3},{%4,%5,%6,%7},{%8,%9},{%0,%1,%2,%3};"
                    : "+f"(c[mi][ni][0]), "+f"(c[mi][ni][1]),
                      "+f"(c[mi][ni][2]), "+f"(c[mi][ni][3])
                    : "r"(a[mi][0]), "r"(a[mi][1]), "r"(a[mi][2]), "r"(a[mi][3]),
                      "r"(b[ni][0]), "r"(b[ni][1]));
    }
}

template<bool FULL>
__device__ __forceinline__ void partials(const float c[4][4][4], int nvalid,
                                         int m0, int n0, int warp_m, int warp_n,
                                         int qid, int tig, int nt) {
#pragma unroll
    for (int mi = 0; mi < 4; mi++) {
        const int r0 = m0 + warp_m * 64 + mi * 16 + qid;
        float mxa = -INFINITY, mxb = -INFINITY;
        float sa = 0.f, sb = 0.f;
#pragma unroll
        for (int ni = 0; ni < 4; ni++) {
            const int cc = warp_n * 32 + ni * 8 + tig * 2;
            if (FULL || cc < nvalid) {
                mxa = fmaxf(mxa, c[mi][ni][0]);
                mxb = fmaxf(mxb, c[mi][ni][2]);
            }
            if (FULL || cc + 1 < nvalid) {
                mxa = fmaxf(mxa, c[mi][ni][1]);
                mxb = fmaxf(mxb, c[mi][ni][3]);
            }
        }
        mxa = fmaxf(mxa, __shfl_xor_sync(0xffffffffu, mxa, 1));
        mxa = fmaxf(mxa, __shfl_xor_sync(0xffffffffu, mxa, 2));
        mxb = fmaxf(mxb, __shfl_xor_sync(0xffffffffu, mxb, 1));
        mxb = fmaxf(mxb, __shfl_xor_sync(0xffffffffu, mxb, 2));
#pragma unroll
        for (int ni = 0; ni < 4; ni++) {
            const int cc = warp_n * 32 + ni * 8 + tig * 2;
            if (FULL || cc < nvalid)     { sa += __expf(c[mi][ni][0] - mxa);
                                           sb += __expf(c[mi][ni][2] - mxb); }
            if (FULL || cc + 1 < nvalid) { sa += __expf(c[mi][ni][1] - mxa);
                                           sb += __expf(c[mi][ni][3] - mxb); }
        }
        sa += __shfl_xor_sync(0xffffffffu, sa, 1);
        sa += __shfl_xor_sync(0xffffffffu, sa, 2);
        sb += __shfl_xor_sync(0xffffffffu, sb, 1);
        sb += __shfl_xor_sync(0xffffffffu, sb, 2);
        if (tig == 0) {
            g_part2[((size_t)r0 * NT_ + nt) * 4 + warp_n]       = make_float2(mxa, sa);
            g_part2[((size_t)(r0 + 8) * NT_ + nt) * 4 + warp_n] = make_float2(mxb, sb);
        }
    }
}

// stage register C -> smem (float2, <=2-way conflicts)
__device__ __forceinline__ void stageC(const float c[4][4][4], float* Cs,
                                       int warp_m, int warp_n, int qid, int tig) {
#pragma unroll
    for (int mi = 0; mi < 4; mi++) {
        const int r0 = warp_m * 64 + mi * 16 + qid;
        float* c0p = Cs + r0 * CPAD + warp_n * 32 + tig * 2;
#pragma unroll
        for (int ni = 0; ni < 4; ni++) {
            *reinterpret_cast<float2*>(c0p + ni * 8) =
                make_float2(c[mi][ni][0], c[mi][ni][1]);
            *reinterpret_cast<float2*>(c0p + ni * 8 + 8 * CPAD) =
                make_float2(c[mi][ni][2], c[mi][ni][3]);
        }
    }
}

// coalesced copy smem C -> out with lse subtraction; alignment by row%4
__device__ __forceinline__ void copyC(const float* Cs, float* __restrict__ out,
                                      int m0, int n0, int nvalid,
                                      int wid, int lane) {
    if (nvalid == 128) {
#pragma unroll
        for (int j = 0; j < 16; j++) {
            const int row = (wid << 4) + j;          // row%4 == j%4
            const float ls = g_lse[m0 + row];
            const float* cs = Cs + row * CPAD;
            float* ob = out + (size_t)(m0 + row) * V_ + n0;
            if ((j & 3) == 0) {                      // 16B-aligned: float4
                int col = lane << 2;
                *reinterpret_cast<float4*>(ob + col) =
                    make_float4(cs[col] - ls, cs[col + 1] - ls,
                                cs[col + 2] - ls, cs[col + 3] - ls);
            } else if (!(j & 1)) {                   // 8B-aligned: float2
#pragma unroll
                for (int k = 0; k < 2; k++) {
                    int col = ((k << 5) + lane) << 1;
                    *reinterpret_cast<float2*>(ob + col) =
                        make_float2(cs[col] - ls, cs[col + 1] - ls);
                }
            } else {                                 // odd: head/tail + f2 body
                if (lane == 0)  ob[0]   = cs[0]   - ls;
                if (lane == 31) ob[127] = cs[127] - ls;
#pragma unroll
                for (int k = 0; k < 2; k++) {
                    int i2 = (k << 5) + lane;
                    if (i2 < 63) {
                        int col = 1 + (i2 << 1);
                        *reinterpret_cast<float2*>(ob + col) =
                            make_float2(cs[col] - ls, cs[col + 1] - ls);
                    }
                }
            }
        }
    } else {
        for (int j = 0; j < 16; j++) {
            const int row = (wid << 4) + j;
            const float ls = g_lse[m0 + row];
            const float* cs = Cs + row * CPAD;
            float* ob = out + (size_t)(m0 + row) * V_ + n0;
            for (int col = lane; col < nvalid; col += 32)
                ob[col] = cs[col] - ls;
        }
    }
}

template<bool WRITE>
__global__ void __launch_bounds__(256, 1)
gemm_pass(float* __restrict__ out) {
    extern __shared__ char smc[];
    const uint32_t sbase = smem_u32(smc);
    float* Cs = reinterpret_cast<float*>(smc + SM_C);

    const int tid = threadIdx.x;
    const int wid = tid >> 5, lane = tid & 31;
    const int warp_m = wid & 1, warp_n = wid >> 1;   // 2(m) x 4(n)
    const int qid = lane >> 2, tig = lane & 3;
    const int m0 = blockIdx.y * 128;

    auto issueB = [&](int nt, int buf) {
        if (nt < NT_) {
            const int n0 = nt * 128;
            const uint32_t d0 = sbase + SM_B0 + (buf << 15);
#pragma unroll
            for (int f = tid; f < 2048; f += 256) {
                int row = f >> 4, c8 = f & 15;
                uint32_t dst = d0 + swz(row, c8);
                const char* src = reinterpret_cast<const char*>(g_negh)
                                + (size_t)(n0 + row) * 256 + c8 * 16;
                asm volatile("cp.async.cg.shared.global [%0], [%1], 16;"
                             :: "r"(dst), "l"(src) : "memory");
            }
        }
        asm volatile("cp.async.commit_group;" ::: "memory");
    };

    issueB(blockIdx.x, 0);
    issueB(blockIdx.x + GX_, 1);

    // ---- stage A tile (g_yh m-block) into swizzled smem ----
#pragma unroll
    for (int f = tid; f < 2048; f += 256) {
        int row = f >> 4, c8 = f & 15;
        uint4 v = *reinterpret_cast<const uint4*>(g_yh + (m0 + row) * E_ + c8 * 8);
        *reinterpret_cast<uint4*>(smc + SM_A + swz(row, c8)) = v;
    }

    int idx = 0;
    for (int nt = blockIdx.x; nt < NT_; nt += GX_, idx++) {
        asm volatile("cp.async.wait_group 1;" ::: "memory");
        __syncthreads();   // B buffer visible; also protects Cs reuse

        const int bsel = idx - (idx / 3) * 3;
        const uint32_t bB = sbase + SM_B0 + (bsel << 15);

        float c[4][4][4];
        mainloop(sbase + SM_A, bB, c, lane, warp_m, warp_n);

        // buffer (bsel+2)%3 was fully consumed in iteration idx-1 -> no barrier
        issueB(nt + 2 * GX_, (bsel + 2 >= 3) ? bsel - 1 : bsel + 2);

        const int n0 = nt * 128;
        const int nvalid = min(128, V_ - n0);

        if (!WRITE) {
            if (nvalid == 128) partials<true >(c, nvalid, m0, n0, warp_m, warp_n, qid, tig, nt);
            else               partials<false>(c, nvalid, m0, n0, warp_m, warp_n, qid, tig, nt);
        } else {
            stageC(c, Cs, warp_m, warp_n, qid, tig);
            __syncthreads();
            copyC(Cs, out, m0, n0, nvalid, wid, lane);
        }
    }
}

// ---------------- K4: combine partials -> lse[b] (256t, float4) -------------
__global__ void lse_kernel() {
    const int b = blockIdx.x, t = threadIdx.x;   // 256 threads
    __shared__ float sm_[256], sl[256];
    const int NQ = NT_ * 2;                      // float4 count (= NT_*4/2)
    const float4* p4 = reinterpret_cast<const float4*>(
        g_part2 + (size_t)b * NT_ * 4);
    float m = -INFINITY, l = 0.f;
    for (int i = t; i < NQ; i += 256) {
        float4 v = p4[i];
        float nm = fmaxf(m, v.x);
        l = l * __expf(m - nm) + v.y * __expf(v.x - nm);
        m = nm;
        nm = fmaxf(m, v.z);
        l = l * __expf(m - nm) + v.w * __expf(v.z - nm);
        m = nm;
    }
    sm_[t] = m; sl[t] = l;
    __syncthreads();
    for (int s = 128; s > 0; s >>= 1) {
        if (t < s) {
            float m2 = sm_[t + s], l2 = sl[t + s];
            float nm = fmaxf(sm_[t], m2);
            sl[t] = sl[t] * __expf(sm_[t] - nm) + l2 * __expf(m2 - nm);
            sm_[t] = nm;
        }
        __syncthreads();
    }
    if (t == 0) g_lse[b] = sm_[0] + logf(sl[0]);
}

extern "C" void kernel_launch(void* const* d_in, const int* in_sizes, int n_in,
                              void* d_out, int out_size) {
    const float* xs     = (const float*)d_in[0];
    const float* metric = (const float*)d_in[1];
    const float* EMB    = (const float*)d_in[2];
    const float* NEG    = (const float*)d_in[3];
    float* out = (float*)d_out;

    prep_kernel<<<3072, 256>>>((const float4*)NEG, (const float4*)xs);
    embed_metric_kernel<<<B_, 128>>>(EMB, metric);

    cudaFuncSetAttribute(gemm_pass<false>,
                         cudaFuncAttributeMaxDynamicSharedMemorySize, SMEM_BYTES);
    cudaFuncSetAttribute(gemm_pass<true>,
                         cudaFuncAttributeMaxDynamicSharedMemorySize, SMEM_BYTES);

    gemm_pass<false><<<dim3(GX_, 8), 256, SMEM_BYTES>>>(out);
    lse_kernel<<<B_, 256>>>();
    gemm_pass<true ><<<dim3(GX_, 8), 256, SMEM_BYTES>>>(out);
}

// round 13
// speedup vs baseline: 1.0961x; 1.0332x over previous
#include <cuda_runtime.h>
#include <cuda_fp16.h>
#include <cstdint>
#include <math.h>

#define B_  1024
#define V_  50257
#define E_  128
#define NT_ 393          // ceil(V_/128)
#define VP_ (NT_ * 128)  // 50304 padded rows
#define GX_ 19           // n-split: 19 x 8 = 152 CTAs = 1 per SM

// ---- scratch (no allocations allowed) ----
__device__ int     g_idx[B_];
__device__ __half  g_yh[B_ * E_];
__device__ __half  g_negh[(size_t)VP_ * E_];      // padded half copy of NEGEMBEDM
__device__ float2  g_part2[(size_t)B_ * NT_ * 4]; // per-(row, tile, warp_n) partials
__device__ float   g_lse[B_];

__device__ __forceinline__ uint32_t smem_u32(const void* p) {
    uint32_t a;
    asm("{ .reg .u64 t; cvta.to.shared.u64 t, %1; cvt.u32.u64 %0, t; }"
        : "=r"(a) : "l"(p));
    return a;
}

// ---------------- K1: conv(NEG->half) + per-row early-exit one-hot scan -----
// blocks 0..1023: scan row blockIdx.x of xs (early exit at hot index).
// blocks 1024..1535: convert NEGEMBEDM fp32 -> padded half.
__global__ void prep_kernel(const float4* __restrict__ neg4,
                            const float* __restrict__ xs) {
    if (blockIdx.x >= 1024) {
        const long n8 = (long)VP_ * E_ / 8;   // 8 halves per iter
        for (long i = (blockIdx.x - 1024) * (long)blockDim.x + threadIdx.x;
             i < n8; i += 512L * blockDim.x) {
            long row = (i * 8) / E_;
            if (row < V_) {
                float4 v0 = neg4[i * 2];
                float4 v1 = neg4[i * 2 + 1];
                __half2 h0 = __float22half2_rn(make_float2(v0.x, v0.y));
                __half2 h1 = __float22half2_rn(make_float2(v0.z, v0.w));
                __half2 h2 = __float22half2_rn(make_float2(v1.x, v1.y));
                __half2 h3 = __float22half2_rn(make_float2(v1.z, v1.w));
                uint4 o = make_uint4(*reinterpret_cast<uint32_t*>(&h0),
                                     *reinterpret_cast<uint32_t*>(&h1),
                                     *reinterpret_cast<uint32_t*>(&h2),
                                     *reinterpret_cast<uint32_t*>(&h3));
                *reinterpret_cast<uint4*>(g_negh + i * 8) = o;
            } else {
                *reinterpret_cast<uint4*>(g_negh + i * 8) = make_uint4(0, 0, 0, 0);
            }
        }
        return;
    }

    // ---- per-row scan with early exit ----
    const int  row = blockIdx.x;
    const long r0f = (long)row * V_;           // first float of this row
    const long a0  = (r0f + 3) & ~3L;          // aligned body start (floats)
    const long a1  = (r0f + V_) & ~3L;         // aligned body end
    __shared__ int found;
    if (threadIdx.x == 0) found = 0;
    __syncthreads();

    // head (<=3 floats) and tail (<=3 floats), checked once
    if (threadIdx.x < 3) {
        long p = r0f + threadIdx.x;
        if (p < a0 && xs[p] != 0.f) { g_idx[row] = (int)(p - r0f); found = 1; }
    } else if (threadIdx.x < 6) {
        long p = a1 + (threadIdx.x - 3);
        if (p < r0f + V_ && xs[p] != 0.f) { g_idx[row] = (int)(p - r0f); found = 1; }
    }

    const float4* body = reinterpret_cast<const float4*>(xs + a0);
    const int n4 = (int)((a1 - a0) >> 2);      // ~12564 float4
    __syncthreads();
    if (found) return;

    for (int base = 0; base < n4; base += 512) {
#pragma unroll
        for (int k = 0; k < 2; k++) {
            int i4 = base + k * 256 + threadIdx.x;
            if (i4 < n4) {
                float4 v = body[i4];
                if (v.x != 0.f || v.y != 0.f || v.z != 0.f || v.w != 0.f) {
                    float vals[4] = {v.x, v.y, v.z, v.w};
#pragma unroll
                    for (int j = 0; j < 4; j++)
                        if (vals[j] != 0.f)
                            g_idx[row] = (int)(a0 - r0f) + i4 * 4 + j;
                    found = 1;
                }
            }
        }
        __syncthreads();
        if (found) break;
        __syncthreads();   // found reread next iter after potential writes
    }
}

// ---------------- K2: y[b] = EMBEDM[idx[b]] @ metric -> half ----------------
__global__ void embed_metric_kernel(const float* __restrict__ EMB,
                                    const float* __restrict__ metric) {
    __shared__ float xe[E_];
    const int b = blockIdx.x, t = threadIdx.x;   // 128 threads
    const int idx = g_idx[b];
    xe[t] = EMB[(size_t)idx * E_ + t];
    __syncthreads();
    float acc = 0.f;
#pragma unroll 8
    for (int k = 0; k < E_; k++) acc += xe[k] * metric[k * E_ + t];
    g_yh[b * E_ + t] = __float2half_rn(acc);
}

// ---------------- K3: persistent fp16 GEMM, two passes ----------------------
#define SM_A   0
#define SM_B0  32768
#define SM_C   131072
#define CPAD   132
#define SMEM_BYTES (131072 + 128 * CPAD * 4)   // 198656

__device__ __forceinline__ uint32_t swz(int row, int c8) {
    return (uint32_t)(row * 256 + ((c8 ^ (row & 7)) << 4));
}

__device__ __forceinline__ void mainloop(uint32_t aB, uint32_t bB,
                                         float c[4][4][4],
                                         int lane, int warp_m, int warp_n) {
#pragma unroll
    for (int mi = 0; mi < 4; mi++)
#pragma unroll
        for (int ni = 0; ni < 4; ni++)
#pragma unroll
            for (int j = 0; j < 4; j++) c[mi][ni][j] = 0.f;

#pragma unroll
    for (int ks = 0; ks < 8; ks++) {
        const int c8a = ks * 2 + (lane >> 4);
        uint32_t a[4][4], b[4][2];
#pragma unroll
        for (int mi = 0; mi < 4; mi++) {
            int row = warp_m * 64 + mi * 16 + (lane & 15);
            uint32_t addr = aB + swz(row, c8a);
            asm volatile("ldmatrix.sync.aligned.m8n8.x4.shared.b16 "
                         "{%0,%1,%2,%3}, [%4];"
                         : "=r"(a[mi][0]), "=r"(a[mi][1]),
                           "=r"(a[mi][2]), "=r"(a[mi][3]) : "r"(addr));
        }
#pragma unroll
        for (int j = 0; j < 2; j++) {
            const int g = lane >> 3;
            int ni_x = 2 * j + (g >> 1);
            int half = g & 1;
            int nrow = warp_n * 32 + ni_x * 8 + (lane & 7);
            uint32_t addr = bB + swz(nrow, ks * 2 + half);
            asm volatile("ldmatrix.sync.aligned.m8n8.x4.shared.b16 "
                         "{%0,%1,%2,%3}, [%4];"
                         : "=r"(b[2 * j][0]), "=r"(b[2 * j][1]),
                           "=r"(b[2 * j + 1][0]), "=r"(b[2 * j + 1][1])
                         : "r"(addr));
        }
#pragma unroll
        for (int mi = 0; mi < 4; mi++)
#pragma unroll
            for (int ni = 0; ni < 4; ni++)
                asm volatile(
                    "mma.sync.aligned.m16n8k16.row.col.f32.f16.f16.f32 "
                    "{%0,%1,%2,%3},{%4,%5,%6,%7},{%8,%9},{%0,%1,%2,%3};"
                    : "+f"(c[mi][ni][0]), "+f"(c[mi][ni][1]),
                      "+f"(c[mi][ni][2]), "+f"(c[mi][ni][3])
                    : "r"(a[mi][0]), "r"(a[mi][1]), "r"(a[mi][2]), "r"(a[mi][3]),
                      "r"(b[ni][0]), "r"(b[ni][1]));
    }
}

template<bool FULL>
__device__ __forceinline__ void partials(const float c[4][4][4], int nvalid,
                                         int m0, int n0, int warp_m, int warp_n,
                                         int qid, int tig, int nt) {
#pragma unroll
    for (int mi = 0; mi < 4; mi++) {
        const int r0 = m0 + warp_m * 64 + mi * 16 + qid;
        float mxa = -INFINITY, mxb = -INFINITY;
        float sa = 0.f, sb = 0.f;
#pragma unroll
        for (int ni = 0; ni < 4; ni++) {
            const int cc = warp_n * 32 + ni * 8 + tig * 2;
            if (FULL || cc < nvalid) {
                mxa = fmaxf(mxa, c[mi][ni][0]);
                mxb = fmaxf(mxb, c[mi][ni][2]);
            }
            if (FULL || cc + 1 < nvalid) {
                mxa = fmaxf(mxa, c[mi][ni][1]);
                mxb = fmaxf(mxb, c[mi][ni][3]);
            }
        }
        mxa = fmaxf(mxa, __shfl_xor_sync(0xffffffffu, mxa, 1));
        mxa = fmaxf(mxa, __shfl_xor_sync(0xffffffffu, mxa, 2));
        mxb = fmaxf(mxb, __shfl_xor_sync(0xffffffffu, mxb, 1));
        mxb = fmaxf(mxb, __shfl_xor_sync(0xffffffffu, mxb, 2));
#pragma unroll
        for (int ni = 0; ni < 4; ni++) {
            const int cc = warp_n * 32 + ni * 8 + tig * 2;
            if (FULL || cc < nvalid)     { sa += __expf(c[mi][ni][0] - mxa);
                                           sb += __expf(c[mi][ni][2] - mxb); }
            if (FULL || cc + 1 < nvalid) { sa += __expf(c[mi][ni][1] - mxa);
                                           sb += __expf(c[mi][ni][3] - mxb); }
        }
        sa += __shfl_xor_sync(0xffffffffu, sa, 1);
        sa += __shfl_xor_sync(0xffffffffu, sa, 2);
        sb += __shfl_xor_sync(0xffffffffu, sb, 1);
        sb += __shfl_xor_sync(0xffffffffu, sb, 2);
        if (tig == 0) {
            g_part2[((size_t)r0 * NT_ + nt) * 4 + warp_n]       = make_float2(mxa, sa);
            g_part2[((size_t)(r0 + 8) * NT_ + nt) * 4 + warp_n] = make_float2(mxb, sb);
        }
    }
}

// stage register C -> smem (float2, <=2-way conflicts)
__device__ __forceinline__ void stageC(const float c[4][4][4], float* Cs,
                                       int warp_m, int warp_n, int qid, int tig) {
#pragma unroll
    for (int mi = 0; mi < 4; mi++) {
        const int r0 = warp_m * 64 + mi * 16 + qid;
        float* c0p = Cs + r0 * CPAD + warp_n * 32 + tig * 2;
#pragma unroll
        for (int ni = 0; ni < 4; ni++) {
            *reinterpret_cast<float2*>(c0p + ni * 8) =
                make_float2(c[mi][ni][0], c[mi][ni][1]);
            *reinterpret_cast<float2*>(c0p + ni * 8 + 8 * CPAD) =
                make_float2(c[mi][ni][2], c[mi][ni][3]);
        }
    }
}

// coalesced copy smem C -> out with lse subtraction; lsr = hoisted lse regs
__device__ __forceinline__ void copyC(const float* Cs, float* __restrict__ out,
                                      int m0, int n0, int nvalid,
                                      int wid, int lane, const float* lsr) {
    if (nvalid == 128) {
#pragma unroll
        for (int j = 0; j < 16; j++) {
            const int row = (wid << 4) + j;          // row%4 == j%4
            const float ls = lsr[j];
            const float* cs = Cs + row * CPAD;
            float* ob = out + (size_t)(m0 + row) * V_ + n0;
            if ((j & 3) == 0) {                      // 16B-aligned: float4
                int col = lane << 2;
                *reinterpret_cast<float4*>(ob + col) =
                    make_float4(cs[col] - ls, cs[col + 1] - ls,
                                cs[col + 2] - ls, cs[col + 3] - ls);
            } else if (!(j & 1)) {                   // 8B-aligned: float2
#pragma unroll
                for (int k = 0; k < 2; k++) {
                    int col = ((k << 5) + lane) << 1;
                    *reinterpret_cast<float2*>(ob + col) =
                        make_float2(cs[col] - ls, cs[col + 1] - ls);
                }
            } else {                                 // odd: head/tail + f2 body
                if (lane == 0)  ob[0]   = cs[0]   - ls;
                if (lane == 31) ob[127] = cs[127] - ls;
#pragma unroll
                for (int k = 0; k < 2; k++) {
                    int i2 = (k << 5) + lane;
                    if (i2 < 63) {
                        int col = 1 + (i2 << 1);
                        *reinterpret_cast<float2*>(ob + col) =
                            make_float2(cs[col] - ls, cs[col + 1] - ls);
                    }
                }
            }
        }
    } else {
        for (int j = 0; j < 16; j++) {
            const int row = (wid << 4) + j;
            const float ls = lsr[j];
            const float* cs = Cs + row * CPAD;
            float* ob = out + (size_t)(m0 + row) * V_ + n0;
            for (int col = lane; col < nvalid; col += 32)
                ob[col] = cs[col] - ls;
        }
    }
}

template<bool WRITE>
__global__ void __launch_bounds__(256, 1)
gemm_pass(float* __restrict__ out) {
    extern __shared__ char smc[];
    const uint32_t sbase = smem_u32(smc);
    float* Cs = reinterpret_cast<float*>(smc + SM_C);

    const int tid = threadIdx.x;
    const int wid = tid >> 5, lane = tid & 31;
    const int warp_m = wid & 1, warp_n = wid >> 1;   // 2(m) x 4(n)
    const int qid = lane >> 2, tig = lane & 3;
    const int m0 = blockIdx.y * 128;

    auto issueB = [&](int nt, int buf) {
        if (nt < NT_) {
            const int n0 = nt * 128;
            const uint32_t d0 = sbase + SM_B0 + (buf << 15);
#pragma unroll
            for (int f = tid; f < 2048; f += 256) {
                int row = f >> 4, c8 = f & 15;
                uint32_t dst = d0 + swz(row, c8);
                const char* src = reinterpret_cast<const char*>(g_negh)
                                + (size_t)(n0 + row) * 256 + c8 * 16;
                asm volatile("cp.async.cg.shared.global [%0], [%1], 16;"
                             :: "r"(dst), "l"(src) : "memory");
            }
        }
        asm volatile("cp.async.commit_group;" ::: "memory");
    };

    issueB(blockIdx.x, 0);
    issueB(blockIdx.x + GX_, 1);

    // ---- stage A tile (g_yh m-block) into swizzled smem ----
#pragma unroll
    for (int f = tid; f < 2048; f += 256) {
        int row = f >> 4, c8 = f & 15;
        uint4 v = *reinterpret_cast<const uint4*>(g_yh + (m0 + row) * E_ + c8 * 8);
        *reinterpret_cast<uint4*>(smc + SM_A + swz(row, c8)) = v;
    }

    // hoist per-warp lse values (loop-invariant; only used when WRITE)
    float lsr[16];
    if (WRITE) {
#pragma unroll
        for (int j = 0; j < 16; j++) lsr[j] = g_lse[m0 + (wid << 4) + j];
    }

    int idx = 0;
    for (int nt = blockIdx.x; nt < NT_; nt += GX_, idx++) {
        asm volatile("cp.async.wait_group 1;" ::: "memory");
        __syncthreads();   // B buffer visible; also protects Cs reuse

        const int bsel = idx - (idx / 3) * 3;
        const uint32_t bB = sbase + SM_B0 + (bsel << 15);

        float c[4][4][4];
        mainloop(sbase + SM_A, bB, c, lane, warp_m, warp_n);

        // buffer (bsel+2)%3 was fully consumed in iteration idx-1 -> no barrier
        issueB(nt + 2 * GX_, (bsel + 2 >= 3) ? bsel - 1 : bsel + 2);

        const int n0 = nt * 128;
        const int nvalid = min(128, V_ - n0);

        if (!WRITE) {
            if (nvalid == 128) partials<true >(c, nvalid, m0, n0, warp_m, warp_n, qid, tig, nt);
            else               partials<false>(c, nvalid, m0, n0, warp_m, warp_n, qid, tig, nt);
        } else {
            stageC(c, Cs, warp_m, warp_n, qid, tig);
            __syncthreads();
            copyC(Cs, out, m0, n0, nvalid, wid, lane, lsr);
        }
    }
}

// ---------------- K4: combine partials -> lse[b] (256t, float4) -------------
__global__ void lse_kernel() {
    const int b = blockIdx.x, t = threadIdx.x;   // 256 threads
    __shared__ float sm_[256], sl[256];
    const int NQ = NT_ * 2;                      // float4 count (= NT_*4/2)
    const float4* p4 = reinterpret_cast<const float4*>(
        g_part2 + (size_t)b * NT_ * 4);
    float m = -INFINITY, l = 0.f;
    for (int i = t; i < NQ; i += 256) {
        float4 v = p4[i];
        float nm = fmaxf(m, v.x);
        l = l * __expf(m - nm) + v.y * __expf(v.x - nm);
        m = nm;
        nm = fmaxf(m, v.z);
        l = l * __expf(m - nm) + v.w * __expf(v.z - nm);
        m = nm;
    }
    sm_[t] = m; sl[t] = l;
    __syncthreads();
    for (int s = 128; s > 0; s >>= 1) {
        if (t < s) {
            float m2 = sm_[t + s], l2 = sl[t + s];
            float nm = fmaxf(sm_[t], m2);
            sl[t] = sl[t] * __expf(sm_[t] - nm) + l2 * __expf(m2 - nm);
            sm_[t] = nm;
        }
        __syncthreads();
    }
    if (t == 0) g_lse[b] = sm_[0] + logf(sl[0]);
}

extern "C" void kernel_launch(void* const* d_in, const int* in_sizes, int n_in,
                              void* d_out, int out_size) {
    const float* xs     = (const float*)d_in[0];
    const float* metric = (const float*)d_in[1];
    const float* EMB    = (const float*)d_in[2];
    const float* NEG    = (const float*)d_in[3];
    float* out = (float*)d_out;

    prep_kernel<<<1536, 256>>>((const float4*)NEG, xs);
    embed_metric_kernel<<<B_, 128>>>(EMB, metric);

    cudaFuncSetAttribute(gemm_pass<false>,
                         cudaFuncAttributeMaxDynamicSharedMemorySize, SMEM_BYTES);
    cudaFuncSetAttribute(gemm_pass<true>,
                         cudaFuncAttributeMaxDynamicSharedMemorySize, SMEM_BYTES);

    gemm_pass<false><<<dim3(GX_, 8), 256, SMEM_BYTES>>>(out);
    lse_kernel<<<B_, 256>>>();
    gemm_pass<true ><<<dim3(GX_, 8), 256, SMEM_BYTES>>>(out);
}

// round 14
// speedup vs baseline: 1.1233x; 1.0248x over previous
#include <cuda_runtime.h>
#include <cuda_fp16.h>
#include <cstdint>
#include <math.h>

#define B_  1024
#define V_  50257
#define E_  128
#define NT_ 393          // ceil(V_/128)
#define VP_ (NT_ * 128)  // 50304 padded rows
#define GX_ 19           // n-split: 19 x 8 = 152 CTAs = 1 per SM

// ---- scratch (no allocations allowed) ----
__device__ int     g_idx[B_];
__device__ __half  g_yh[B_ * E_];
__device__ __half  g_negh[(size_t)VP_ * E_];      // padded half copy of NEGEMBEDM
__device__ float2  g_part2[(size_t)B_ * NT_ * 4]; // per-(row, tile, warp_n) partials
__device__ float   g_lse[B_];

__device__ __forceinline__ uint32_t smem_u32(const void* p) {
    uint32_t a;
    asm("{ .reg .u64 t; cvta.to.shared.u64 t, %1; cvt.u32.u64 %0, t; }"
        : "=r"(a) : "l"(p));
    return a;
}

// ---------------- K1: conv(NEG->half) + per-row early-exit one-hot scan -----
__global__ void prep_kernel(const float4* __restrict__ neg4,
                            const float* __restrict__ xs) {
    if (blockIdx.x >= 1024) {
        const long n8 = (long)VP_ * E_ / 8;   // 8 halves per iter
        for (long i = (blockIdx.x - 1024) * (long)blockDim.x + threadIdx.x;
             i < n8; i += 512L * blockDim.x) {
            long row = (i * 8) / E_;
            if (row < V_) {
                float4 v0 = neg4[i * 2];
                float4 v1 = neg4[i * 2 + 1];
                __half2 h0 = __float22half2_rn(make_float2(v0.x, v0.y));
                __half2 h1 = __float22half2_rn(make_float2(v0.z, v0.w));
                __half2 h2 = __float22half2_rn(make_float2(v1.x, v1.y));
                __half2 h3 = __float22half2_rn(make_float2(v1.z, v1.w));
                uint4 o = make_uint4(*reinterpret_cast<uint32_t*>(&h0),
                                     *reinterpret_cast<uint32_t*>(&h1),
                                     *reinterpret_cast<uint32_t*>(&h2),
                                     *reinterpret_cast<uint32_t*>(&h3));
                *reinterpret_cast<uint4*>(g_negh + i * 8) = o;
            } else {
                *reinterpret_cast<uint4*>(g_negh + i * 8) = make_uint4(0, 0, 0, 0);
            }
        }
        return;
    }

    const int  row = blockIdx.x;
    const long r0f = (long)row * V_;
    const long a0  = (r0f + 3) & ~3L;
    const long a1  = (r0f + V_) & ~3L;
    __shared__ int found;
    if (threadIdx.x == 0) found = 0;
    __syncthreads();

    if (threadIdx.x < 3) {
        long p = r0f + threadIdx.x;
        if (p < a0 && xs[p] != 0.f) { g_idx[row] = (int)(p - r0f); found = 1; }
    } else if (threadIdx.x < 6) {
        long p = a1 + (threadIdx.x - 3);
        if (p < r0f + V_ && xs[p] != 0.f) { g_idx[row] = (int)(p - r0f); found = 1; }
    }

    const float4* body = reinterpret_cast<const float4*>(xs + a0);
    const int n4 = (int)((a1 - a0) >> 2);
    __syncthreads();
    if (found) return;

    for (int base = 0; base < n4; base += 512) {
#pragma unroll
        for (int k = 0; k < 2; k++) {
            int i4 = base + k * 256 + threadIdx.x;
            if (i4 < n4) {
                float4 v = body[i4];
                if (v.x != 0.f || v.y != 0.f || v.z != 0.f || v.w != 0.f) {
                    float vals[4] = {v.x, v.y, v.z, v.w};
#pragma unroll
                    for (int j = 0; j < 4; j++)
                        if (vals[j] != 0.f)
                            g_idx[row] = (int)(a0 - r0f) + i4 * 4 + j;
                    found = 1;
                }
            }
        }
        __syncthreads();
        if (found) break;
        __syncthreads();
    }
}

// ---------------- K2: y[b] = EMBEDM[idx[b]] @ metric -> half ----------------
__global__ void embed_metric_kernel(const float* __restrict__ EMB,
                                    const float* __restrict__ metric) {
    __shared__ float xe[E_];
    const int b = blockIdx.x, t = threadIdx.x;   // 128 threads
    const int idx = g_idx[b];
    xe[t] = EMB[(size_t)idx * E_ + t];
    __syncthreads();
    float acc = 0.f;
#pragma unroll 8
    for (int k = 0; k < E_; k++) acc += xe[k] * metric[k * E_ + t];
    g_yh[b * E_ + t] = __float2half_rn(acc);
}

// ---------------- K3: persistent fp16 GEMM, two passes ----------------------
// Pass 1: A @0 | B0/B1/B2 @32768 (3 bufs, distance-2)          smem 131072
// Pass 2: A @0 | B0/B1 @32768 (2 bufs, distance-1) | C0 @98304 | C1 @163840
//         C is 128x128 floats, XOR-swizzled at 16B chunks.     smem 229376
#define SM_A    0
#define SM_B0   32768
#define SM_C0   98304
#define SM_C1   163840
#define SMEM_P1 131072
#define SMEM_P2 229376

__device__ __forceinline__ uint32_t swz(int row, int c8) {
    return (uint32_t)(row * 256 + ((c8 ^ (row & 7)) << 4));
}

__device__ __forceinline__ void mainloop(uint32_t aB, uint32_t bB,
                                         float c[4][4][4],
                                         int lane, int warp_m, int warp_n) {
#pragma unroll
    for (int mi = 0; mi < 4; mi++)
#pragma unroll
        for (int ni = 0; ni < 4; ni++)
#pragma unroll
            for (int j = 0; j < 4; j++) c[mi][ni][j] = 0.f;

#pragma unroll
    for (int ks = 0; ks < 8; ks++) {
        const int c8a = ks * 2 + (lane >> 4);
        uint32_t a[4][4], b[4][2];
#pragma unroll
        for (int mi = 0; mi < 4; mi++) {
            int row = warp_m * 64 + mi * 16 + (lane & 15);
            uint32_t addr = aB + swz(row, c8a);
            asm volatile("ldmatrix.sync.aligned.m8n8.x4.shared.b16 "
                         "{%0,%1,%2,%3}, [%4];"
                         : "=r"(a[mi][0]), "=r"(a[mi][1]),
                           "=r"(a[mi][2]), "=r"(a[mi][3]) : "r"(addr));
        }
#pragma unroll
        for (int j = 0; j < 2; j++) {
            const int g = lane >> 3;
            int ni_x = 2 * j + (g >> 1);
            int half = g & 1;
            int nrow = warp_n * 32 + ni_x * 8 + (lane & 7);
            uint32_t addr = bB + swz(nrow, ks * 2 + half);
            asm volatile("ldmatrix.sync.aligned.m8n8.x4.shared.b16 "
                         "{%0,%1,%2,%3}, [%4];"
                         : "=r"(b[2 * j][0]), "=r"(b[2 * j][1]),
                           "=r"(b[2 * j + 1][0]), "=r"(b[2 * j + 1][1])
                         : "r"(addr));
        }
#pragma unroll
        for (int mi = 0; mi < 4; mi++)
#pragma unroll
            for (int ni = 0; ni < 4; ni++)
                asm volatile(
                    "mma.sync.aligned.m16n8k16.row.col.f32.f16.f16.f32 "
                    "{%0,%1,%2,%3},{%4,%5,%6,%7},{%8,%9},{%0,%1,%2,%3};"
                    : "+f"(c[mi][ni][0]), "+f"(c[mi][ni][1]),
                      "+f"(c[mi][ni][2]), "+f"(c[mi][ni][3])
                    : "r"(a[mi][0]), "r"(a[mi][1]), "r"(a[mi][2]), "r"(a[mi][3]),
                      "r"(b[ni][0]), "r"(b[ni][1]));
    }
}

template<bool FULL>
__device__ __forceinline__ void partials(const float c[4][4][4], int nvalid,
                                         int m0, int n0, int warp_m, int warp_n,
                                         int qid, int tig, int nt) {
#pragma unroll
    for (int mi = 0; mi < 4; mi++) {
        const int r0 = m0 + warp_m * 64 + mi * 16 + qid;
        float mxa = -INFINITY, mxb = -INFINITY;
        float sa = 0.f, sb = 0.f;
#pragma unroll
        for (int ni = 0; ni < 4; ni++) {
            const int cc = warp_n * 32 + ni * 8 + tig * 2;
            if (FULL || cc < nvalid) {
                mxa = fmaxf(mxa, c[mi][ni][0]);
                mxb = fmaxf(mxb, c[mi][ni][2]);
            }
            if (FULL || cc + 1 < nvalid) {
                mxa = fmaxf(mxa, c[mi][ni][1]);
                mxb = fmaxf(mxb, c[mi][ni][3]);
            }
        }
        mxa = fmaxf(mxa, __shfl_xor_sync(0xffffffffu, mxa, 1));
        mxa = fmaxf(mxa, __shfl_xor_sync(0xffffffffu, mxa, 2));
        mxb = fmaxf(mxb, __shfl_xor_sync(0xffffffffu, mxb, 1));
        mxb = fmaxf(mxb, __shfl_xor_sync(0xffffffffu, mxb, 2));
#pragma unroll
        for (int ni = 0; ni < 4; ni++) {
            const int cc = warp_n * 32 + ni * 8 + tig * 2;
            if (FULL || cc < nvalid)     { sa += __expf(c[mi][ni][0] - mxa);
                                           sb += __expf(c[mi][ni][2] - mxb); }
            if (FULL || cc + 1 < nvalid) { sa += __expf(c[mi][ni][1] - mxa);
                                           sb += __expf(c[mi][ni][3] - mxb); }
        }
        sa += __shfl_xor_sync(0xffffffffu, sa, 1);
        sa += __shfl_xor_sync(0xffffffffu, sa, 2);
        sb += __shfl_xor_sync(0xffffffffu, sb, 1);
        sb += __shfl_xor_sync(0xffffffffu, sb, 2);
        if (tig == 0) {
            g_part2[((size_t)r0 * NT_ + nt) * 4 + warp_n]       = make_float2(mxa, sa);
            g_part2[((size_t)(r0 + 8) * NT_ + nt) * 4 + warp_n] = make_float2(mxb, sb);
        }
    }
}

// stage register C -> swizzled smem C (float2; <=2-way conflicts)
__device__ __forceinline__ void stageC(const float c[4][4][4], float* Cs,
                                       int warp_m, int warp_n, int qid, int tig) {
#pragma unroll
    for (int mi = 0; mi < 4; mi++) {
        const int r0 = warp_m * 64 + mi * 16 + qid;    // r0&7 == qid
#pragma unroll
        for (int ni = 0; ni < 4; ni++) {
            const int col = warp_n * 32 + ni * 8 + tig * 2;
            const int off = (((col >> 2) ^ qid) << 2) + (col & 3);
            *reinterpret_cast<float2*>(Cs + (r0 << 7) + off) =
                make_float2(c[mi][ni][0], c[mi][ni][1]);
            *reinterpret_cast<float2*>(Cs + ((r0 + 8) << 7) + off) =
                make_float2(c[mi][ni][2], c[mi][ni][3]);
        }
    }
}

// coalesced copy swizzled smem C -> out with lse subtraction
__device__ __forceinline__ void copyC(const float* Cs, float* __restrict__ out,
                                      int m0, int n0, int nvalid,
                                      int wid, int lane, const float* lsr) {
    if (nvalid == 128) {
#pragma unroll
        for (int j = 0; j < 16; j++) {
            const int row = (wid << 4) + j;          // row%4 == j%4
            const int r7 = row & 7;
            const float ls = lsr[j];
            const float* cr = Cs + (row << 7);
            float* ob = out + (size_t)(m0 + row) * V_ + n0;
            if ((j & 3) == 0) {                      // 16B-aligned: float4
                const float4 v = *reinterpret_cast<const float4*>(
                    cr + ((lane ^ r7) << 2));
                *reinterpret_cast<float4*>(ob + (lane << 2)) =
                    make_float4(v.x - ls, v.y - ls, v.z - ls, v.w - ls);
            } else if (!(j & 1)) {                   // 8B-aligned: float2
#pragma unroll
                for (int k = 0; k < 2; k++) {
                    int col = ((k << 5) + lane) << 1;
                    const float2 v = *reinterpret_cast<const float2*>(
                        cr + ((((col >> 2) ^ r7) << 2) + (col & 3)));
                    *reinterpret_cast<float2*>(ob + col) =
                        make_float2(v.x - ls, v.y - ls);
                }
            } else {                                 // odd: head/tail + body
                if (lane == 0)  ob[0]   = cr[r7 << 2] - ls;
                if (lane == 31) ob[127] = cr[((31 ^ r7) << 2) + 3] - ls;
#pragma unroll
                for (int k = 0; k < 2; k++) {
                    int i2 = (k << 5) + lane;
                    if (i2 < 63) {
                        int col = 1 + (i2 << 1);
                        float va = cr[(((col >> 2) ^ r7) << 2) + (col & 3)];
                        int c2 = col + 1;
                        float vb = cr[(((c2 >> 2) ^ r7) << 2) + (c2 & 3)];
                        *reinterpret_cast<float2*>(ob + col) =
                            make_float2(va - ls, vb - ls);
                    }
                }
            }
        }
    } else {
        for (int j = 0; j < 16; j++) {
            const int row = (wid << 4) + j;
            const int r7 = row & 7;
            const float ls = lsr[j];
            const float* cr = Cs + (row << 7);
            float* ob = out + (size_t)(m0 + row) * V_ + n0;
            for (int col = lane; col < nvalid; col += 32)
                ob[col] = cr[(((col >> 2) ^ r7) << 2) + (col & 3)] - ls;
        }
    }
}

template<bool WRITE>
__global__ void __launch_bounds__(256, 1)
gemm_pass(float* __restrict__ out) {
    extern __shared__ char smc[];
    const uint32_t sbase = smem_u32(smc);

    const int tid = threadIdx.x;
    const int wid = tid >> 5, lane = tid & 31;
    const int warp_m = wid & 1, warp_n = wid >> 1;   // 2(m) x 4(n)
    const int qid = lane >> 2, tig = lane & 3;
    const int m0 = blockIdx.y * 128;

    auto issueB = [&](int nt, int buf) {
        if (nt < NT_) {
            const int n0 = nt * 128;
            const uint32_t d0 = sbase + SM_B0 + (buf << 15);
#pragma unroll
            for (int f = tid; f < 2048; f += 256) {
                int row = f >> 4, c8 = f & 15;
                uint32_t dst = d0 + swz(row, c8);
                const char* src = reinterpret_cast<const char*>(g_negh)
                                + (size_t)(n0 + row) * 256 + c8 * 16;
                asm volatile("cp.async.cg.shared.global [%0], [%1], 16;"
                             :: "r"(dst), "l"(src) : "memory");
            }
        }
        asm volatile("cp.async.commit_group;" ::: "memory");
    };

    issueB(blockIdx.x, 0);
    if (!WRITE) issueB(blockIdx.x + GX_, 1);

    // ---- stage A tile (g_yh m-block) into swizzled smem ----
#pragma unroll
    for (int f = tid; f < 2048; f += 256) {
        int row = f >> 4, c8 = f & 15;
        uint4 v = *reinterpret_cast<const uint4*>(g_yh + (m0 + row) * E_ + c8 * 8);
        *reinterpret_cast<uint4*>(smc + SM_A + swz(row, c8)) = v;
    }

    if (!WRITE) {
        // ---------------- pass 1: partials only, 3-buffer distance-2 --------
        int idx = 0;
        for (int nt = blockIdx.x; nt < NT_; nt += GX_, idx++) {
            asm volatile("cp.async.wait_group 1;" ::: "memory");
            __syncthreads();

            const int bsel = idx - (idx / 3) * 3;
            float c[4][4][4];
            mainloop(sbase + SM_A, sbase + SM_B0 + (bsel << 15),
                     c, lane, warp_m, warp_n);
            issueB(nt + 2 * GX_, (bsel + 2 >= 3) ? bsel - 1 : bsel + 2);

            const int n0 = nt * 128;
            const int nvalid = min(128, V_ - n0);
            if (nvalid == 128) partials<true >(c, nvalid, m0, n0, warp_m, warp_n, qid, tig, nt);
            else               partials<false>(c, nvalid, m0, n0, warp_m, warp_n, qid, tig, nt);
        }
    } else {
        // ---------------- pass 2: pipelined epilogue, 2xB + 2xC -------------
        float* C0 = reinterpret_cast<float*>(smc + SM_C0);
        float* C1 = reinterpret_cast<float*>(smc + SM_C1);

        float lsr[16];
#pragma unroll
        for (int j = 0; j < 16; j++) lsr[j] = g_lse[m0 + (wid << 4) + j];

        int pn0 = -1, pnv = 0;
        int idx = 0;
        for (int nt = blockIdx.x; nt < NT_; nt += GX_, idx++) {
            asm volatile("cp.async.wait_group 0;" ::: "memory");
            __syncthreads();   // B(idx) visible; stage(idx-1) + copy(idx-2) done

            issueB(nt + GX_, (idx + 1) & 1);   // overwrites B(idx-1): consumed

            if (pn0 >= 0)      // copy tile idx-1 (overlaps mainloop's DRAM shadow)
                copyC((idx & 1) ? C0 : C1, out, m0, pn0, pnv, wid, lane, lsr);

            float c[4][4][4];
            mainloop(sbase + SM_A, sbase + SM_B0 + ((idx & 1) << 15),
                     c, lane, warp_m, warp_n);

            stageC(c, (idx & 1) ? C1 : C0, warp_m, warp_n, qid, tig);

            pn0 = nt * 128;
            pnv = min(128, V_ - pn0);
        }
        __syncthreads();       // last stage complete
        copyC(((idx - 1) & 1) ? C1 : C0, out, m0, pn0, pnv, wid, lane, lsr);
    }
}

// ---------------- K4: combine partials -> lse[b] (256t, float4) -------------
__global__ void lse_kernel() {
    const int b = blockIdx.x, t = threadIdx.x;   // 256 threads
    __shared__ float sm_[256], sl[256];
    const int NQ = NT_ * 2;
    const float4* p4 = reinterpret_cast<const float4*>(
        g_part2 + (size_t)b * NT_ * 4);
    float m = -INFINITY, l = 0.f;
    for (int i = t; i < NQ; i += 256) {
        float4 v = p4[i];
        float nm = fmaxf(m, v.x);
        l = l * __expf(m - nm) + v.y * __expf(v.x - nm);
        m = nm;
        nm = fmaxf(m, v.z);
        l = l * __expf(m - nm) + v.w * __expf(v.z - nm);
        m = nm;
    }
    sm_[t] = m; sl[t] = l;
    __syncthreads();
    for (int s = 128; s > 0; s >>= 1) {
        if (t < s) {
            float m2 = sm_[t + s], l2 = sl[t + s];
            float nm = fmaxf(sm_[t], m2);
            sl[t] = sl[t] * __expf(sm_[t] - nm) + l2 * __expf(m2 - nm);
            sm_[t] = nm;
        }
        __syncthreads();
    }
    if (t == 0) g_lse[b] = sm_[0] + logf(sl[0]);
}

extern "C" void kernel_launch(void* const* d_in, const int* in_sizes, int n_in,
                              void* d_out, int out_size) {
    const float* xs     = (const float*)d_in[0];
    const float* metric = (const float*)d_in[1];
    const float* EMB    = (const float*)d_in[2];
    const float* NEG    = (const float*)d_in[3];
    float* out = (float*)d_out;

    prep_kernel<<<1536, 256>>>((const float4*)NEG, xs);
    embed_metric_kernel<<<B_, 128>>>(EMB, metric);

    cudaFuncSetAttribute(gemm_pass<false>,
                         cudaFuncAttributeMaxDynamicSharedMemorySize, SMEM_P1);
    cudaFuncSetAttribute(gemm_pass<true>,
                         cudaFuncAttributeMaxDynamicSharedMemorySize, SMEM_P2);

    gemm_pass<false><<<dim3(GX_, 8), 256, SMEM_P1>>>(out);
    lse_kernel<<<B_, 256>>>();
    gemm_pass<true ><<<dim3(GX_, 8), 256, SMEM_P2>>>(out);
}

// round 15
// speedup vs baseline: 1.2045x; 1.0724x over previous
#include <cuda_runtime.h>
#include <cuda_fp16.h>
#include <cstdint>
#include <math.h>

#define B_  1024
#define V_  50257
#define E_  128
#define NT_ 393          // ceil(V_/128)
#define VP_ (NT_ * 128)  // 50304 padded rows
#define GX_ 19           // n-split: 19 x 8 = 152 CTAs = 1 per SM
#define NP_ 76           // partials per row: 19 CTAs x 4 warp_n

// ---- scratch (no allocations allowed) ----
__device__ __half  g_yh[B_ * E_];
__device__ __half  g_negh[(size_t)VP_ * E_];   // padded half copy of NEGEMBEDM
__device__ float2  g_part2[(size_t)B_ * NP_];  // per-(row, bx, warp_n) partials
__device__ float   g_lse[B_];

__device__ __forceinline__ uint32_t smem_u32(const void* p) {
    uint32_t a;
    asm("{ .reg .u64 t; cvta.to.shared.u64 t, %1; cvt.u32.u64 %0, t; }"
        : "=r"(a) : "l"(p));
    return a;
}

// ------- K1: conv(NEG->half) + per-row early-exit scan + fused embed --------
// blocks 0..1023: scan row blockIdx.x of xs, then y[row] = EMB[idx] @ metric.
// blocks 1024..1535: convert NEGEMBEDM fp32 -> padded half.
__global__ void prep_kernel(const float4* __restrict__ neg4,
                            const float* __restrict__ xs,
                            const float* __restrict__ EMB,
                            const float* __restrict__ metric) {
    if (blockIdx.x >= 1024) {
        const long n8 = (long)VP_ * E_ / 8;   // 8 halves per iter
        for (long i = (blockIdx.x - 1024) * (long)blockDim.x + threadIdx.x;
             i < n8; i += 512L * blockDim.x) {
            long row = (i * 8) / E_;
            if (row < V_) {
                float4 v0 = neg4[i * 2];
                float4 v1 = neg4[i * 2 + 1];
                __half2 h0 = __float22half2_rn(make_float2(v0.x, v0.y));
                __half2 h1 = __float22half2_rn(make_float2(v0.z, v0.w));
                __half2 h2 = __float22half2_rn(make_float2(v1.x, v1.y));
                __half2 h3 = __float22half2_rn(make_float2(v1.z, v1.w));
                uint4 o = make_uint4(*reinterpret_cast<uint32_t*>(&h0),
                                     *reinterpret_cast<uint32_t*>(&h1),
                                     *reinterpret_cast<uint32_t*>(&h2),
                                     *reinterpret_cast<uint32_t*>(&h3));
                *reinterpret_cast<uint4*>(g_negh + i * 8) = o;
            } else {
                *reinterpret_cast<uint4*>(g_negh + i * 8) = make_uint4(0, 0, 0, 0);
            }
        }
        return;
    }

    const int  row = blockIdx.x;
    const int  tid = threadIdx.x;
    const long r0f = (long)row * V_;
    const long a0  = (r0f + 3) & ~3L;
    const long a1  = (r0f + V_) & ~3L;
    __shared__ int s_found, s_idx;
    __shared__ float xe[E_];
    if (tid == 0) s_found = 0;
    __syncthreads();

    // head (<=3) and tail (<=3) scalars
    if (tid < 3) {
        long p = r0f + tid;
        if (p < a0 && xs[p] != 0.f) { s_idx = (int)(p - r0f); s_found = 1; }
    } else if (tid < 6) {
        long p = a1 + (tid - 3);
        if (p < r0f + V_ && xs[p] != 0.f) { s_idx = (int)(p - r0f); s_found = 1; }
    }
    __syncthreads();

    if (!s_found) {
        const float4* body = reinterpret_cast<const float4*>(xs + a0);
        const int n4 = (int)((a1 - a0) >> 2);
        for (int base = 0; base < n4; base += 2048) {   // 32KB per round
#pragma unroll
            for (int k = 0; k < 8; k++) {
                int i4 = base + k * 256 + tid;
                if (i4 < n4) {
                    float4 v = body[i4];
                    if (v.x != 0.f || v.y != 0.f || v.z != 0.f || v.w != 0.f) {
                        float vals[4] = {v.x, v.y, v.z, v.w};
#pragma unroll
                        for (int j = 0; j < 4; j++)
                            if (vals[j] != 0.f)
                                s_idx = (int)(a0 - r0f) + i4 * 4 + j;
                        s_found = 1;
                    }
                }
            }
            __syncthreads();          // (A) writes visible, uniform decision
            if (s_found) break;
            __syncthreads();          // (B) reads done before next writes
        }
    }
    __syncthreads();

    // ---- fused embed: y[row] = EMB[idx] @ metric -> half ----
    const int idx = s_idx;
    if (tid < E_) xe[tid] = EMB[(size_t)idx * E_ + tid];
    __syncthreads();
    if (tid < E_) {
        float acc = 0.f;
#pragma unroll 8
        for (int k = 0; k < E_; k++) acc += xe[k] * metric[k * E_ + tid];
        g_yh[row * E_ + tid] = __float2half_rn(acc);
    }
}

// ---------------- K3: persistent fp16 GEMM, two passes ----------------------
// Pass 1: A @0 | B0/B1/B2 @32768 (3 bufs, distance-2); register-resident
//         running softmax partials, written ONCE at the end.
// Pass 2: A @0 | B0/B1 @32768 (2 bufs, distance-1) | C0 @98304 | C1 @163840
#define SM_A    0
#define SM_B0   32768
#define SM_C0   98304
#define SM_C1   163840
#define SMEM_P1 131072
#define SMEM_P2 229376

__device__ __forceinline__ uint32_t swz(int row, int c8) {
    return (uint32_t)(row * 256 + ((c8 ^ (row & 7)) << 4));
}

__device__ __forceinline__ void mainloop(uint32_t aB, uint32_t bB,
                                         float c[4][4][4],
                                         int lane, int warp_m, int warp_n) {
#pragma unroll
    for (int mi = 0; mi < 4; mi++)
#pragma unroll
        for (int ni = 0; ni < 4; ni++)
#pragma unroll
            for (int j = 0; j < 4; j++) c[mi][ni][j] = 0.f;

#pragma unroll
    for (int ks = 0; ks < 8; ks++) {
        const int c8a = ks * 2 + (lane >> 4);
        uint32_t a[4][4], b[4][2];
#pragma unroll
        for (int mi = 0; mi < 4; mi++) {
            int row = warp_m * 64 + mi * 16 + (lane & 15);
            uint32_t addr = aB + swz(row, c8a);
            asm volatile("ldmatrix.sync.aligned.m8n8.x4.shared.b16 "
                         "{%0,%1,%2,%3}, [%4];"
                         : "=r"(a[mi][0]), "=r"(a[mi][1]),
                           "=r"(a[mi][2]), "=r"(a[mi][3]) : "r"(addr));
        }
#pragma unroll
        for (int j = 0; j < 2; j++) {
            const int g = lane >> 3;
            int ni_x = 2 * j + (g >> 1);
            int half = g & 1;
            int nrow = warp_n * 32 + ni_x * 8 + (lane & 7);
            uint32_t addr = bB + swz(nrow, ks * 2 + half);
            asm volatile("ldmatrix.sync.aligned.m8n8.x4.shared.b16 "
                         "{%0,%1,%2,%3}, [%4];"
                         : "=r"(b[2 * j][0]), "=r"(b[2 * j][1]),
                           "=r"(b[2 * j + 1][0]), "=r"(b[2 * j + 1][1])
                         : "r"(addr));
        }
#pragma unroll
        for (int mi = 0; mi < 4; mi++)
#pragma unroll
            for (int ni = 0; ni < 4; ni++)
                asm volatile(
                    "mma.sync.aligned.m16n8k16.row.col.f32.f16.f16.f32 "
                    "{%0,%1,%2,%3},{%4,%5,%6,%7},{%8,%9},{%0,%1,%2,%3};"
                    : "+f"(c[mi][ni][0]), "+f"(c[mi][ni][1]),
                      "+f"(c[mi][ni][2]), "+f"(c[mi][ni][3])
                    : "r"(a[mi][0]), "r"(a[mi][1]), "r"(a[mi][2]), "r"(a[mi][3]),
                      "r"(b[ni][0]), "r"(b[ni][1]));
    }
}

// per-tile online merge into register-resident running (max, sum)
template<bool FULL>
__device__ __forceinline__ void accumulate(const float c[4][4][4], int nvalid,
                                           float rm[4][2], float rl[4][2],
                                           int warp_n, int tig) {
#pragma unroll
    for (int mi = 0; mi < 4; mi++) {
        float mxa = -INFINITY, mxb = -INFINITY, sa = 0.f, sb = 0.f;
#pragma unroll
        for (int ni = 0; ni < 4; ni++) {
            const int cc = warp_n * 32 + ni * 8 + tig * 2;
            if (FULL || cc < nvalid) {
                mxa = fmaxf(mxa, c[mi][ni][0]);
                mxb = fmaxf(mxb, c[mi][ni][2]);
            }
            if (FULL || cc + 1 < nvalid) {
                mxa = fmaxf(mxa, c[mi][ni][1]);
                mxb = fmaxf(mxb, c[mi][ni][3]);
            }
        }
#pragma unroll
        for (int ni = 0; ni < 4; ni++) {
            const int cc = warp_n * 32 + ni * 8 + tig * 2;
            if (FULL || cc < nvalid)     { sa += __expf(c[mi][ni][0] - mxa);
                                           sb += __expf(c[mi][ni][2] - mxb); }
            if (FULL || cc + 1 < nvalid) { sa += __expf(c[mi][ni][1] - mxa);
                                           sb += __expf(c[mi][ni][3] - mxb); }
        }
        // merge (safe: running max is finite after the first full tile)
        float nm = fmaxf(rm[mi][0], mxa);
        rl[mi][0] = rl[mi][0] * __expf(rm[mi][0] - nm) + sa * __expf(mxa - nm);
        rm[mi][0] = nm;
        nm = fmaxf(rm[mi][1], mxb);
        rl[mi][1] = rl[mi][1] * __expf(rm[mi][1] - nm) + sb * __expf(mxb - nm);
        rm[mi][1] = nm;
    }
}

// stage register C -> swizzled smem C (float2; <=2-way conflicts)
__device__ __forceinline__ void stageC(const float c[4][4][4], float* Cs,
                                       int warp_m, int warp_n, int qid, int tig) {
#pragma unroll
    for (int mi = 0; mi < 4; mi++) {
        const int r0 = warp_m * 64 + mi * 16 + qid;    // r0&7 == qid
#pragma unroll
        for (int ni = 0; ni < 4; ni++) {
            const int col = warp_n * 32 + ni * 8 + tig * 2;
            const int off = (((col >> 2) ^ qid) << 2) + (col & 3);
            *reinterpret_cast<float2*>(Cs + (r0 << 7) + off) =
                make_float2(c[mi][ni][0], c[mi][ni][1]);
            *reinterpret_cast<float2*>(Cs + ((r0 + 8) << 7) + off) =
                make_float2(c[mi][ni][2], c[mi][ni][3]);
        }
    }
}

// coalesced copy swizzled smem C -> out with lse subtraction
__device__ __forceinline__ void copyC(const float* Cs, float* __restrict__ out,
                                      int m0, int n0, int nvalid,
                                      int wid, int lane, const float* lsr) {
    if (nvalid == 128) {
#pragma unroll
        for (int j = 0; j < 16; j++) {
            const int row = (wid << 4) + j;          // row%4 == j%4
            const int r7 = row & 7;
            const float ls = lsr[j];
            const float* cr = Cs + (row << 7);
            float* ob = out + (size_t)(m0 + row) * V_ + n0;
            if ((j & 3) == 0) {                      // 16B-aligned: float4
                const float4 v = *reinterpret_cast<const float4*>(
                    cr + ((lane ^ r7) << 2));
                *reinterpret_cast<float4*>(ob + (lane << 2)) =
                    make_float4(v.x - ls, v.y - ls, v.z - ls, v.w - ls);
            } else if (!(j & 1)) {                   // 8B-aligned: float2
#pragma unroll
                for (int k = 0; k < 2; k++) {
                    int col = ((k << 5) + lane) << 1;
                    const float2 v = *reinterpret_cast<const float2*>(
                        cr + ((((col >> 2) ^ r7) << 2) + (col & 3)));
                    *reinterpret_cast<float2*>(ob + col) =
                        make_float2(v.x - ls, v.y - ls);
                }
            } else {                                 // odd: head/tail + body
                if (lane == 0)  ob[0]   = cr[r7 << 2] - ls;
                if (lane == 31) ob[127] = cr[((31 ^ r7) << 2) + 3] - ls;
#pragma unroll
                for (int k = 0; k < 2; k++) {
                    int i2 = (k << 5) + lane;
                    if (i2 < 63) {
                        int col = 1 + (i2 << 1);
                        float va = cr[(((col >> 2) ^ r7) << 2) + (col & 3)];
                        int c2 = col + 1;
                        float vb = cr[(((c2 >> 2) ^ r7) << 2) + (c2 & 3)];
                        *reinterpret_cast<float2*>(ob + col) =
                            make_float2(va - ls, vb - ls);
                    }
                }
            }
        }
    } else {
        for (int j = 0; j < 16; j++) {
            const int row = (wid << 4) + j;
            const int r7 = row & 7;
            const float ls = lsr[j];
            const float* cr = Cs + (row << 7);
            float* ob = out + (size_t)(m0 + row) * V_ + n0;
            for (int col = lane; col < nvalid; col += 32)
                ob[col] = cr[(((col >> 2) ^ r7) << 2) + (col & 3)] - ls;
        }
    }
}

template<bool WRITE>
__global__ void __launch_bounds__(256, 1)
gemm_pass(float* __restrict__ out) {
    extern __shared__ char smc[];
    const uint32_t sbase = smem_u32(smc);

    const int tid = threadIdx.x;
    const int wid = tid >> 5, lane = tid & 31;
    const int warp_m = wid & 1, warp_n = wid >> 1;   // 2(m) x 4(n)
    const int qid = lane >> 2, tig = lane & 3;
    const int m0 = blockIdx.y * 128;

    auto issueB = [&](int nt, int buf) {
        if (nt < NT_) {
            const int n0 = nt * 128;
            const uint32_t d0 = sbase + SM_B0 + (buf << 15);
#pragma unroll
            for (int f = tid; f < 2048; f += 256) {
                int row = f >> 4, c8 = f & 15;
                uint32_t dst = d0 + swz(row, c8);
                const char* src = reinterpret_cast<const char*>(g_negh)
                                + (size_t)(n0 + row) * 256 + c8 * 16;
                asm volatile("cp.async.cg.shared.global [%0], [%1], 16;"
                             :: "r"(dst), "l"(src) : "memory");
            }
        }
        asm volatile("cp.async.commit_group;" ::: "memory");
    };

    issueB(blockIdx.x, 0);
    if (!WRITE) issueB(blockIdx.x + GX_, 1);

    // ---- stage A tile (g_yh m-block) into swizzled smem ----
#pragma unroll
    for (int f = tid; f < 2048; f += 256) {
        int row = f >> 4, c8 = f & 15;
        uint4 v = *reinterpret_cast<const uint4*>(g_yh + (m0 + row) * E_ + c8 * 8);
        *reinterpret_cast<uint4*>(smc + SM_A + swz(row, c8)) = v;
    }

    if (!WRITE) {
        // -------- pass 1: running register partials, 3-buffer distance-2 ----
        float rm[4][2], rl[4][2];
#pragma unroll
        for (int mi = 0; mi < 4; mi++) {
            rm[mi][0] = rm[mi][1] = -INFINITY;
            rl[mi][0] = rl[mi][1] = 0.f;
        }

        int idx = 0;
        for (int nt = blockIdx.x; nt < NT_; nt += GX_, idx++) {
            asm volatile("cp.async.wait_group 1;" ::: "memory");
            __syncthreads();

            const int bsel = idx - (idx / 3) * 3;
            float c[4][4][4];
            mainloop(sbase + SM_A, sbase + SM_B0 + (bsel << 15),
                     c, lane, warp_m, warp_n);
            issueB(nt + 2 * GX_, (bsel + 2 >= 3) ? bsel - 1 : bsel + 2);

            const int nvalid = min(128, V_ - nt * 128);
            if (nvalid == 128) accumulate<true >(c, nvalid, rm, rl, warp_n, tig);
            else               accumulate<false>(c, nvalid, rm, rl, warp_n, tig);
        }

        // combine across tig lanes, write one partial per row
#pragma unroll
        for (int mi = 0; mi < 4; mi++)
#pragma unroll
            for (int h = 0; h < 2; h++) {
                float m = rm[mi][h], l = rl[mi][h];
#pragma unroll
                for (int s = 1; s <= 2; s <<= 1) {
                    float m2 = __shfl_xor_sync(0xffffffffu, m, s);
                    float l2 = __shfl_xor_sync(0xffffffffu, l, s);
                    float nm = fmaxf(m, m2);
                    l = l * __expf(m - nm) + l2 * __expf(m2 - nm);
                    m = nm;
                }
                if (tig == 0) {
                    int row = m0 + warp_m * 64 + mi * 16 + qid + h * 8;
                    g_part2[(size_t)row * NP_ + blockIdx.x * 4 + warp_n] =
                        make_float2(m, l);
                }
            }
    } else {
        // -------- pass 2: pipelined epilogue, 2xB + 2xC ----------------------
        float* C0 = reinterpret_cast<float*>(smc + SM_C0);
        float* C1 = reinterpret_cast<float*>(smc + SM_C1);

        float lsr[16];
#pragma unroll
        for (int j = 0; j < 16; j++) lsr[j] = g_lse[m0 + (wid << 4) + j];

        int pn0 = -1, pnv = 0;
        int idx = 0;
        for (int nt = blockIdx.x; nt < NT_; nt += GX_, idx++) {
            asm volatile("cp.async.wait_group 0;" ::: "memory");
            __syncthreads();   // B(idx) visible; stage(idx-1) + copy(idx-2) done

            issueB(nt + GX_, (idx + 1) & 1);

            if (pn0 >= 0)
                copyC((idx & 1) ? C0 : C1, out, m0, pn0, pnv, wid, lane, lsr);

            float c[4][4][4];
            mainloop(sbase + SM_A, sbase + SM_B0 + ((idx & 1) << 15),
                     c, lane, warp_m, warp_n);

            stageC(c, (idx & 1) ? C1 : C0, warp_m, warp_n, qid, tig);

            pn0 = nt * 128;
            pnv = min(128, V_ - pn0);
        }
        __syncthreads();
        copyC(((idx - 1) & 1) ? C1 : C0, out, m0, pn0, pnv, wid, lane, lsr);
    }
}

// ---------------- K4: combine 76 partials -> lse[b] (1 warp / row) ----------
__global__ void lse_kernel() {
    const int b = blockIdx.x, lane = threadIdx.x;   // 32 threads
    const float2* p = g_part2 + (size_t)b * NP_;
    float m = -INFINITY, l = 0.f;
    for (int i = lane; i < NP_; i += 32) {
        float2 v = p[i];
        float nm = fmaxf(m, v.x);
        l = l * __expf(m - nm) + v.y * __expf(v.x - nm);
        m = nm;
    }
#pragma unroll
    for (int s = 16; s > 0; s >>= 1) {
        float m2 = __shfl_xor_sync(0xffffffffu, m, s);
        float l2 = __shfl_xor_sync(0xffffffffu, l, s);
        float nm = fmaxf(m, m2);
        l = l * __expf(m - nm) + l2 * __expf(m2 - nm);
        m = nm;
    }
    if (lane == 0) g_lse[b] = m + logf(l);
}

extern "C" void kernel_launch(void* const* d_in, const int* in_sizes, int n_in,
                              void* d_out, int out_size) {
    const float* xs     = (const float*)d_in[0];
    const float* metric = (const float*)d_in[1];
    const float* EMB    = (const float*)d_in[2];
    const float* NEG    = (const float*)d_in[3];
    float* out = (float*)d_out;

    prep_kernel<<<1536, 256>>>((const float4*)NEG, xs, EMB, metric);

    cudaFuncSetAttribute(gemm_pass<false>,
                         cudaFuncAttributeMaxDynamicSharedMemorySize, SMEM_P1);
    cudaFuncSetAttribute(gemm_pass<true>,
                         cudaFuncAttributeMaxDynamicSharedMemorySize, SMEM_P2);

    gemm_pass<false><<<dim3(GX_, 8), 256, SMEM_P1>>>(out);
    lse_kernel<<<B_, 32>>>();
    gemm_pass<true ><<<dim3(GX_, 8), 256, SMEM_P2>>>(out);
}